// round 1
// baseline (speedup 1.0000x reference)
#include <cuda_runtime.h>

#define BATCH 256

// ---------------- intermediate scratch (device globals; no allocs) ----------
__device__ float g_h1[BATCH*3*15*15*15*15];   // 155.5 MB
__device__ float g_h2[BATCH*3*12*12*12*12];   //  63.7 MB
__device__ float g_h3[BATCH*4*9*9*9*9];       //  26.9 MB
__device__ float g_h4[BATCH*5*6*6*6*6];       //   6.6 MB
__device__ float g_h5[BATCH*5*4*4*4*4];       //   1.3 MB

// ---------------------------------------------------------------------------
// Generic 4D conv, valid padding, stride 1. Block = (batch, y-tile, z-tile).
// SMEM holds the full (W,X) extent and a haloed (Y,Z) window for all Cin.
// Each thread owns one (ow,ox) column and register-tiles acc[COUT][TY][TZ].
// Weights staged in SMEM as [cin][kw][kx][ky][kz][cout] (broadcast loads).
// ---------------------------------------------------------------------------
template<int CIN,int COUT,int S,int K,int TY,int TZ,int BDIM>
__global__ __launch_bounds__(BDIM)
void conv4d_yz(const float* __restrict__ in, const float* __restrict__ wt,
               const float* __restrict__ bias, float* __restrict__ out)
{
    constexpr int O   = S - K + 1;
    constexpr int TYI = TY + K - 1, TZI = TZ + K - 1;
    constexpr int NTY = (O + TY - 1) / TY, NTZ = (O + TZ - 1) / TZ;
    constexpr int ISZ = CIN * S * S * TYI * TZI;
    constexpr int WSZ = COUT * CIN * K * K * K * K;

    extern __shared__ float sm[];
    float* si = sm;          // input tile
    float* sw = sm + ISZ;    // weights (rearranged)

    const int tid = threadIdx.x;
    int bid = blockIdx.x;
    const int tzb = bid % NTZ; bid /= NTZ;
    const int tyb = bid % NTY;
    const int b   = bid / NTY;
    const int y0 = tyb * TY, z0 = tzb * TZ;

    // stage weights: gmem [c][cin][kw][kx][ky][kz] -> smem [cin][kw][kx][ky][kz][c]
    for (int i = tid; i < WSZ; i += BDIM) {
        int c = i / (CIN*K*K*K*K);
        int r = i - c * (CIN*K*K*K*K);
        sw[r * COUT + c] = wt[i];
    }
    // stage input tile (guard y/z halo overrun at the last tiles)
    const float* inb = in + (b * CIN) * S * S * S * S;
    for (int i = tid; i < ISZ; i += BDIM) {
        int zz = i % TZI; int t = i / TZI;
        int iy = t % TYI; t /= TYI;
        int xx = t % S;   t /= S;
        int ww = t % S;   int cin = t / S;
        int gy = y0 + iy, gz = z0 + zz;
        float v = 0.f;
        if (gy < S && gz < S)
            v = inb[(((cin * S + ww) * S + xx) * S + gy) * S + gz];
        si[i] = v;
    }
    __syncthreads();

    for (int pos = tid; pos < O * O; pos += BDIM) {
        const int ow = pos / O, ox = pos - ow * O;

        float acc[COUT][TY][TZ];
        #pragma unroll
        for (int c = 0; c < COUT; c++) {
            float bv = bias[c];
            #pragma unroll
            for (int ty = 0; ty < TY; ty++)
                #pragma unroll
                for (int tz = 0; tz < TZ; tz++) acc[c][ty][tz] = bv;
        }

        #pragma unroll 1
        for (int cin = 0; cin < CIN; cin++)
        #pragma unroll 1
        for (int kw = 0; kw < K; kw++)
        #pragma unroll 1
        for (int kx = 0; kx < K; kx++) {
            // hoist K*K*COUT weights for this (cin,kw,kx) into registers
            const float* wp = sw + (((cin * K + kw) * K + kx) * K * K) * COUT;
            float wr[K * K * COUT];
            #pragma unroll
            for (int i = 0; i < K * K * COUT; i++) wr[i] = wp[i];

            const float* ip = si + ((cin * S + ow + kw) * S + ox + kx) * TYI * TZI;
            #pragma unroll
            for (int iy = 0; iy < TYI; iy++) {
                float row[TZI];
                #pragma unroll
                for (int zz = 0; zz < TZI; zz++) row[zz] = ip[iy * TZI + zz];
                #pragma unroll
                for (int ky = 0; ky < K; ky++) {
                    const int oy = iy - ky;
                    if (oy >= 0 && oy < TY) {
                        #pragma unroll
                        for (int kz = 0; kz < K; kz++)
                        #pragma unroll
                        for (int tz = 0; tz < TZ; tz++)
                        #pragma unroll
                        for (int c = 0; c < COUT; c++)
                            acc[c][oy][tz] = fmaf(row[tz + kz],
                                                  wr[(ky * K + kz) * COUT + c],
                                                  acc[c][oy][tz]);
                    }
                }
            }
        }

        float* outb = out + (b * COUT) * O * O * O * O;
        #pragma unroll
        for (int c = 0; c < COUT; c++)
        #pragma unroll
        for (int ty = 0; ty < TY; ty++)
        #pragma unroll
        for (int tz = 0; tz < TZ; tz++) {
            int oy = y0 + ty, oz = z0 + tz;
            if (oy < O && oz < O)
                outb[(((c * O + ow) * O + ox) * O + oy) * O + oz] =
                    fmaxf(acc[c][ty][tz], 0.f);
        }
    }
}

// ---------------------------------------------------------------------------
// Whole-input-in-SMEM conv for small layers. Thread = (ow,ox,oy), full Z in regs.
// ---------------------------------------------------------------------------
template<int CIN,int COUT,int S,int K,int BDIM>
__global__ __launch_bounds__(BDIM)
void conv4d_fullz(const float* __restrict__ in, const float* __restrict__ wt,
                  const float* __restrict__ bias, float* __restrict__ out)
{
    constexpr int O   = S - K + 1;
    constexpr int ISZ = CIN * S * S * S * S;
    constexpr int WSZ = COUT * CIN * K * K * K * K;
    extern __shared__ float sm[];
    float* si = sm; float* sw = sm + ISZ;
    const int tid = threadIdx.x, b = blockIdx.x;

    for (int i = tid; i < WSZ; i += BDIM) {
        int c = i / (CIN*K*K*K*K); int r = i - c * (CIN*K*K*K*K);
        sw[r * COUT + c] = wt[i];
    }
    const float* inb = in + b * ISZ;
    for (int i = tid; i < ISZ; i += BDIM) si[i] = inb[i];
    __syncthreads();

    for (int pos = tid; pos < O * O * O; pos += BDIM) {
        int oy = pos % O; int t = pos / O;
        int ox = t % O;   int ow = t / O;

        float acc[COUT][O];
        #pragma unroll
        for (int c = 0; c < COUT; c++) {
            float bv = bias[c];
            #pragma unroll
            for (int z = 0; z < O; z++) acc[c][z] = bv;
        }
        #pragma unroll 1
        for (int cin = 0; cin < CIN; cin++)
        #pragma unroll 1
        for (int kw = 0; kw < K; kw++)
        #pragma unroll 1
        for (int kx = 0; kx < K; kx++) {
            const float* plane = si + ((cin * S + ow + kw) * S + ox + kx) * S * S;
            #pragma unroll
            for (int ky = 0; ky < K; ky++) {
                float row[S];
                #pragma unroll
                for (int z = 0; z < S; z++) row[z] = plane[(oy + ky) * S + z];
                const float* wp = sw + ((((cin*K + kw)*K + kx)*K + ky) * K) * COUT;
                float wr[K * COUT];
                #pragma unroll
                for (int i = 0; i < K * COUT; i++) wr[i] = wp[i];
                #pragma unroll
                for (int kz = 0; kz < K; kz++)
                #pragma unroll
                for (int z = 0; z < O; z++)
                #pragma unroll
                for (int c = 0; c < COUT; c++)
                    acc[c][z] = fmaf(row[z + kz], wr[kz * COUT + c], acc[c][z]);
            }
        }
        float* outb = out + b * COUT * O * O * O * O;
        #pragma unroll
        for (int c = 0; c < COUT; c++)
        #pragma unroll
        for (int z = 0; z < O; z++)
            outb[(((c * O + ow) * O + ox) * O + oy) * O + z] = fmaxf(acc[c][z], 0.f);
    }
}

// ---------------------------------------------------------------------------
// Tiny last conv: thread = one (ow,ox,oy,oz) point, all COUT channels.
// ---------------------------------------------------------------------------
template<int CIN,int COUT,int S,int K,int BDIM>
__global__ __launch_bounds__(BDIM)
void conv4d_point(const float* __restrict__ in, const float* __restrict__ wt,
                  const float* __restrict__ bias, float* __restrict__ out)
{
    constexpr int O   = S - K + 1;
    constexpr int ISZ = CIN * S * S * S * S;
    constexpr int WSZ = COUT * CIN * K * K * K * K;
    extern __shared__ float sm[];
    float* si = sm; float* sw = sm + ISZ;
    const int tid = threadIdx.x, b = blockIdx.x;

    for (int i = tid; i < WSZ; i += BDIM) {
        int c = i / (CIN*K*K*K*K); int r = i - c * (CIN*K*K*K*K);
        sw[r * COUT + c] = wt[i];
    }
    const float* inb = in + b * ISZ;
    for (int i = tid; i < ISZ; i += BDIM) si[i] = inb[i];
    __syncthreads();

    for (int pos = tid; pos < O * O * O * O; pos += BDIM) {
        int oz = pos % O; int t = pos / O;
        int oy = t % O;   t /= O;
        int ox = t % O;   int ow = t / O;

        float acc[COUT];
        #pragma unroll
        for (int c = 0; c < COUT; c++) acc[c] = bias[c];

        #pragma unroll 1
        for (int cin = 0; cin < CIN; cin++)
        #pragma unroll 1
        for (int kw = 0; kw < K; kw++)
        #pragma unroll 1
        for (int kx = 0; kx < K; kx++) {
            const float* plane = si + ((cin * S + ow + kw) * S + ox + kx) * S * S;
            #pragma unroll
            for (int ky = 0; ky < K; ky++) {
                const float* r  = plane + (oy + ky) * S + oz;
                const float* wp = sw + ((((cin*K + kw)*K + kx)*K + ky) * K) * COUT;
                #pragma unroll
                for (int kz = 0; kz < K; kz++)
                #pragma unroll
                for (int c = 0; c < COUT; c++)
                    acc[c] = fmaf(r[kz], wp[kz * COUT + c], acc[c]);
            }
        }
        float* outb = out + b * COUT * O * O * O * O;
        #pragma unroll
        for (int c = 0; c < COUT; c++)
            outb[(((c * O + ow) * O + ox) * O + oy) * O + oz] = fmaxf(acc[c], 0.f);
    }
}

// ---------------------------------------------------------------------------
// Fused dense1(relu) + dense2 + softmax. One block per batch row.
// ---------------------------------------------------------------------------
__global__ __launch_bounds__(256)
void dense_head(const float* __restrict__ h, const float* __restrict__ dw1,
                const float* __restrict__ db1, const float* __restrict__ dw2,
                const float* __restrict__ db2, float* __restrict__ out)
{
    __shared__ float srow[1280];
    __shared__ float g[33];
    const int b = blockIdx.x, tid = threadIdx.x;

    for (int i = tid; i < 1280; i += 256) srow[i] = h[b * 1280 + i];
    __syncthreads();

    // 4 lanes per output feature; lanes with f>=33 idle through, reconverge at shfl
    const int f = tid >> 2, p = tid & 3;
    float s = 0.f;
    if (f < 33) {
        const float* wrow = dw1 + f * 1280;
        for (int k = p; k < 1280; k += 4) s = fmaf(srow[k], wrow[k], s);
    }
    s += __shfl_xor_sync(0xffffffffu, s, 1);
    s += __shfl_xor_sync(0xffffffffu, s, 2);
    if (p == 0 && f < 33) g[f] = fmaxf(s + db1[f], 0.f);
    __syncthreads();

    if (tid == 0) {
        float l0 = db2[0], l1 = db2[1];
        #pragma unroll
        for (int j = 0; j < 33; j++) {
            l0 = fmaf(g[j], dw2[j], l0);
            l1 = fmaf(g[j], dw2[33 + j], l1);
        }
        float m  = fmaxf(l0, l1);
        float e0 = expf(l0 - m), e1 = expf(l1 - m);
        float inv = 1.f / (e0 + e1);
        out[b * 2 + 0] = e0 * inv;
        out[b * 2 + 1] = e1 * inv;
    }
}

// ---------------------------------------------------------------------------
extern "C" void kernel_launch(void* const* d_in, const int* in_sizes, int n_in,
                              void* d_out, int out_size)
{
    (void)in_sizes; (void)n_in; (void)out_size;
    const float* x   = (const float*)d_in[0];
    const float* w1  = (const float*)d_in[1];  const float* b1  = (const float*)d_in[2];
    const float* w2  = (const float*)d_in[3];  const float* b2  = (const float*)d_in[4];
    const float* w3  = (const float*)d_in[5];  const float* b3  = (const float*)d_in[6];
    const float* w4  = (const float*)d_in[7];  const float* b4  = (const float*)d_in[8];
    const float* w5  = (const float*)d_in[9];  const float* b5  = (const float*)d_in[10];
    const float* dw1 = (const float*)d_in[11]; const float* db1 = (const float*)d_in[12];
    const float* dw2 = (const float*)d_in[13]; const float* db2 = (const float*)d_in[14];
    float* out = (float*)d_out;

    void *p1, *p2, *p3, *p4, *p5;
    cudaGetSymbolAddress(&p1, g_h1);
    cudaGetSymbolAddress(&p2, g_h2);
    cudaGetSymbolAddress(&p3, g_h3);
    cudaGetSymbolAddress(&p4, g_h4);
    cudaGetSymbolAddress(&p5, g_h5);
    float *h1 = (float*)p1, *h2 = (float*)p2, *h3 = (float*)p3,
          *h4 = (float*)p4, *h5 = (float*)p5;

    constexpr int SM1 = (1*18*18*7*7 + 3*1*256) * 4;   //  66.6 KB
    constexpr int SM2 = (3*15*15*7*7 + 3*3*256) * 4;   // 141.5 KB
    constexpr int SM3 = (3*12*12*6*6 + 4*3*256) * 4;   //  74.5 KB
    constexpr int SM4 = (4*9*9*9*9   + 5*4*256) * 4;   // 125.5 KB
    constexpr int SM5 = (5*6*6*6*6   + 5*5*81)  * 4;   //  34.0 KB

    cudaFuncSetAttribute((const void*)conv4d_yz<1,3,18,4,4,4,256>,
                         cudaFuncAttributeMaxDynamicSharedMemorySize, SM1);
    cudaFuncSetAttribute((const void*)conv4d_yz<3,3,15,4,4,4,160>,
                         cudaFuncAttributeMaxDynamicSharedMemorySize, SM2);
    cudaFuncSetAttribute((const void*)conv4d_yz<3,4,12,4,3,3,96>,
                         cudaFuncAttributeMaxDynamicSharedMemorySize, SM3);
    cudaFuncSetAttribute((const void*)conv4d_fullz<4,5,9,4,224>,
                         cudaFuncAttributeMaxDynamicSharedMemorySize, SM4);
    cudaFuncSetAttribute((const void*)conv4d_point<5,5,6,3,256>,
                         cudaFuncAttributeMaxDynamicSharedMemorySize, SM5);

    // L1: 18^4 -> 15^4, 4x4 yz tiles
    conv4d_yz<1,3,18,4,4,4,256><<<BATCH*4*4, 256, SM1>>>(x,  w1, b1, h1);
    // L2: 15^4 -> 12^4, 3x3 yz tiles (exact)
    conv4d_yz<3,3,15,4,4,4,160><<<BATCH*3*3, 160, SM2>>>(h1, w2, b2, h2);
    // L3: 12^4 -> 9^4, 3x3 yz tiles (exact)
    conv4d_yz<3,4,12,4,3,3,96><<<BATCH*3*3,  96,  SM3>>>(h2, w3, b3, h3);
    // L4: 9^4 -> 6^4, whole input in SMEM
    conv4d_fullz<4,5,9,4,224><<<BATCH, 224, SM4>>>(h3, w4, b4, h4);
    // L5: 6^4 -> 4^4 (k=3)
    conv4d_point<5,5,6,3,256><<<BATCH, 256, SM5>>>(h4, w5, b5, h5);
    // Head
    dense_head<<<BATCH, 256>>>(h5, dw1, db1, dw2, db2, out);
}

// round 2
// speedup vs baseline: 1.1836x; 1.1836x over previous
#include <cuda_runtime.h>

#define BATCH 256

// ---------------- intermediate scratch (device globals; no allocs) ----------
__device__ float g_h1[BATCH*3*15*15*15*15];   // 155.5 MB
__device__ float g_h2[BATCH*3*12*12*12*12];   //  63.7 MB
__device__ float g_h3[BATCH*4*9*9*9*9];       //  26.9 MB
__device__ float g_h4[BATCH*5*6*6*6*6];       //   6.6 MB
__device__ float g_h5[BATCH*5*4*4*4*4];       //   1.3 MB

typedef unsigned long long u64;

// ---- packed f32x2 helpers (ptxas never emits FFMA2 from C++; PTX only) ----
__device__ __forceinline__ u64 pk2(float lo, float hi) {
    u64 d; asm("mov.b64 %0, {%1, %2};" : "=l"(d) : "f"(lo), "f"(hi)); return d;
}
__device__ __forceinline__ void unpk2(u64 v, float& lo, float& hi) {
    asm("mov.b64 {%0, %1}, %2;" : "=f"(lo), "=f"(hi) : "l"(v));
}
__device__ __forceinline__ u64 fma2(u64 a, u64 b, u64 c) {
    u64 d; asm("fma.rn.f32x2 %0, %1, %2, %3;" : "=l"(d) : "l"(a), "l"(b), "l"(c));
    return d;
}

// ---------------------------------------------------------------------------
// 4D conv, valid, stride 1, FFMA2 over Z pairs. Block = (batch, y-tile, z-tile).
// cin staged in CCH-sized SMEM chunks (acc persists in regs; needs BDIM >= O*O).
// Weights live in SMEM as duplicated 64-bit pairs -> LDS.64 broadcast hoists.
// ---------------------------------------------------------------------------
template<int CIN,int COUT,int S,int K,int CCH,int TY,int TZ,int BDIM,int MINB>
__global__ __launch_bounds__(BDIM, MINB)
void conv4d_yz_f2(const float* __restrict__ in, const float* __restrict__ wt,
                  const float* __restrict__ bias, float* __restrict__ out)
{
    static_assert(TZ % 2 == 0, "TZ must be even");
    constexpr int O   = S - K + 1;
    static_assert(BDIM >= O * O, "one pos pass required");
    constexpr int TYI = TY + K - 1, TZI = TZ + K - 1;
    constexpr int NTY = (O + TY - 1) / TY, NTZ = (O + TZ - 1) / TZ;
    constexpr int ISZ = CCH * S * S * TYI * TZI;            // floats per chunk
    constexpr int WSZ = COUT * CIN * K * K * K * K;         // u64 entries
    constexpr int NCH = (CIN + CCH - 1) / CCH;
    constexpr int TZP = TZ / 2;

    extern __shared__ u64 smu[];
    u64*   sw2 = smu;                       // duplicated weight pairs
    float* si  = (float*)(smu + WSZ);       // input chunk

    const int tid = threadIdx.x;
    int bid = blockIdx.x;
    const int tzb = bid % NTZ; bid /= NTZ;
    const int tyb = bid % NTY;
    const int b   = bid / NTY;
    const int y0 = tyb * TY, z0 = tzb * TZ;

    // weights: gmem [c][cin][kw][kx][ky][kz] -> smem pairs [cin][kw][kx][ky][kz][c]
    for (int i = tid; i < WSZ; i += BDIM) {
        int c = i / (CIN*K*K*K*K);
        int r = i - c * (CIN*K*K*K*K);
        float w = wt[i];
        sw2[r * COUT + c] = pk2(w, w);
    }

    const int pos = tid;
    const int ow  = pos / O, ox = pos - ow * O;
    const bool active = (pos < O * O);

    u64 acc[COUT][TY][TZP];
    #pragma unroll
    for (int c = 0; c < COUT; c++) {
        float bv = bias[c];
        u64 bp = pk2(bv, bv);
        #pragma unroll
        for (int ty = 0; ty < TY; ty++)
            #pragma unroll
            for (int t = 0; t < TZP; t++) acc[c][ty][t] = bp;
    }

    const float* inb = in + (size_t)b * CIN * S * S * S * S;

    for (int cc = 0; cc < NCH; cc++) {
        __syncthreads();
        // stage chunk [cc*CCH, cc*CCH+CCH)
        for (int i = tid; i < ISZ; i += BDIM) {
            int zz = i % TZI; int t = i / TZI;
            int iy = t % TYI; t /= TYI;
            int xx = t % S;   t /= S;
            int ww = t % S;   int ci = t / S;
            int gy = y0 + iy, gz = z0 + zz;
            float v = 0.f;
            if (gy < S && gz < S)
                v = inb[((((cc*CCH + ci) * S + ww) * S + xx) * S + gy) * S + gz];
            si[i] = v;
        }
        __syncthreads();

        if (active) {
            #pragma unroll
            for (int ci = 0; ci < CCH; ci++)
            #pragma unroll 1
            for (int kw = 0; kw < K; kw++)
            #pragma unroll 1
            for (int kx = 0; kx < K; kx++) {
                const float* ip = si + ((ci * S + ow + kw) * S + ox + kx) * TYI * TZI;
                const u64* wb = sw2 + ((((cc*CCH + ci) * K + kw) * K + kx) * K) * K * COUT;
                #pragma unroll
                for (int ky = 0; ky < K; ky++) {
                    u64 wr[K * COUT];                 // LDS.64 broadcast hoist
                    #pragma unroll
                    for (int i = 0; i < K * COUT; i++) wr[i] = wb[ky * K * COUT + i];
                    #pragma unroll
                    for (int ty = 0; ty < TY; ty++) {
                        const float* rp0 = ip + (ky + ty) * TZI;
                        float row[TZI];
                        #pragma unroll
                        for (int z = 0; z < TZI; z++) row[z] = rp0[z];
                        u64 rp[TZI - 1];
                        #pragma unroll
                        for (int j = 0; j < TZI - 1; j++) rp[j] = pk2(row[j], row[j+1]);
                        #pragma unroll
                        for (int kz = 0; kz < K; kz++)
                        #pragma unroll
                        for (int t = 0; t < TZP; t++)
                        #pragma unroll
                        for (int c = 0; c < COUT; c++)
                            acc[c][ty][t] = fma2(rp[kz + 2*t], wr[kz*COUT + c],
                                                 acc[c][ty][t]);
                    }
                }
            }
        }
    }

    if (active) {
        float* outb = out + (size_t)b * COUT * O * O * O * O;
        #pragma unroll
        for (int c = 0; c < COUT; c++)
        #pragma unroll
        for (int ty = 0; ty < TY; ty++)
        #pragma unroll
        for (int t = 0; t < TZP; t++) {
            float lo, hi; unpk2(acc[c][ty][t], lo, hi);
            int oy = y0 + ty, oz0 = z0 + 2*t;
            if (oy < O) {
                size_t base = (((size_t)(c * O + ow) * O + ox) * O + oy) * O;
                if (oz0     < O) outb[base + oz0]     = fmaxf(lo, 0.f);
                if (oz0 + 1 < O) outb[base + oz0 + 1] = fmaxf(hi, 0.f);
            }
        }
    }
}

// ---------------------------------------------------------------------------
// FFMA2 whole-spatial conv (L4): thread = (ow,ox,oy), Z packed, cin chunked.
// ---------------------------------------------------------------------------
template<int CIN,int COUT,int S,int K,int CCH,int BDIM,int MINB>
__global__ __launch_bounds__(BDIM, MINB)
void conv4d_fullz_f2(const float* __restrict__ in, const float* __restrict__ wt,
                     const float* __restrict__ bias, float* __restrict__ out)
{
    constexpr int O   = S - K + 1;
    static_assert(O % 2 == 0 && BDIM >= O*O*O, "");
    constexpr int OZP = O / 2;
    constexpr int ISZ = CCH * S * S * S * S;
    constexpr int WSZ = COUT * CIN * K * K * K * K;
    constexpr int NCH = (CIN + CCH - 1) / CCH;

    extern __shared__ u64 smu[];
    u64*   sw2 = smu;
    float* si  = (float*)(smu + WSZ);

    const int tid = threadIdx.x, b = blockIdx.x;

    for (int i = tid; i < WSZ; i += BDIM) {
        int c = i / (CIN*K*K*K*K);
        int r = i - c * (CIN*K*K*K*K);
        float w = wt[i];
        sw2[r * COUT + c] = pk2(w, w);
    }

    const int pos = tid;
    int oy = pos % O, t0 = pos / O;
    int ox = t0 % O, ow = t0 / O;
    const bool active = (pos < O * O * O);

    u64 acc[COUT][OZP];
    #pragma unroll
    for (int c = 0; c < COUT; c++) {
        float bv = bias[c];
        u64 bp = pk2(bv, bv);
        #pragma unroll
        for (int t = 0; t < OZP; t++) acc[c][t] = bp;
    }

    const float* inb = in + (size_t)b * CIN * S * S * S * S;

    for (int cc = 0; cc < NCH; cc++) {
        __syncthreads();
        for (int i = tid; i < ISZ; i += BDIM) si[i] = inb[cc * ISZ + i];
        __syncthreads();

        if (active) {
            #pragma unroll
            for (int ci = 0; ci < CCH; ci++)
            #pragma unroll 1
            for (int kw = 0; kw < K; kw++)
            #pragma unroll 1
            for (int kx = 0; kx < K; kx++) {
                const float* plane = si + ((ci * S + ow + kw) * S + ox + kx) * S * S;
                const u64* wb = sw2 + ((((cc*CCH + ci) * K + kw) * K + kx) * K) * K * COUT;
                #pragma unroll
                for (int ky = 0; ky < K; ky++) {
                    u64 wr[K * COUT];
                    #pragma unroll
                    for (int i = 0; i < K * COUT; i++) wr[i] = wb[ky * K * COUT + i];
                    const float* rowp = plane + (oy + ky) * S;
                    float row[S];
                    #pragma unroll
                    for (int z = 0; z < S; z++) row[z] = rowp[z];
                    u64 rp[S - 1];
                    #pragma unroll
                    for (int j = 0; j < S - 1; j++) rp[j] = pk2(row[j], row[j+1]);
                    #pragma unroll
                    for (int kz = 0; kz < K; kz++)
                    #pragma unroll
                    for (int t = 0; t < OZP; t++)
                    #pragma unroll
                    for (int c = 0; c < COUT; c++)
                        acc[c][t] = fma2(rp[kz + 2*t], wr[kz*COUT + c], acc[c][t]);
                }
            }
        }
    }

    if (active) {
        float* outb = out + (size_t)b * COUT * O * O * O * O;
        #pragma unroll
        for (int c = 0; c < COUT; c++)
        #pragma unroll
        for (int t = 0; t < OZP; t++) {
            float lo, hi; unpk2(acc[c][t], lo, hi);
            size_t base = (((size_t)(c * O + ow) * O + ox) * O + oy) * O;
            outb[base + 2*t]     = fmaxf(lo, 0.f);
            outb[base + 2*t + 1] = fmaxf(hi, 0.f);
        }
    }
}

// ---------------------------------------------------------------------------
// Tiny last conv: thread = one (ow,ox,oy,oz) point, all COUT channels (scalar).
// ---------------------------------------------------------------------------
template<int CIN,int COUT,int S,int K,int BDIM>
__global__ __launch_bounds__(BDIM)
void conv4d_point(const float* __restrict__ in, const float* __restrict__ wt,
                  const float* __restrict__ bias, float* __restrict__ out)
{
    constexpr int O   = S - K + 1;
    constexpr int ISZ = CIN * S * S * S * S;
    constexpr int WSZ = COUT * CIN * K * K * K * K;
    extern __shared__ float sm[];
    float* si = sm; float* sw = sm + ISZ;
    const int tid = threadIdx.x, b = blockIdx.x;

    for (int i = tid; i < WSZ; i += BDIM) {
        int c = i / (CIN*K*K*K*K); int r = i - c * (CIN*K*K*K*K);
        sw[r * COUT + c] = wt[i];
    }
    const float* inb = in + (size_t)b * ISZ;
    for (int i = tid; i < ISZ; i += BDIM) si[i] = inb[i];
    __syncthreads();

    for (int pos = tid; pos < O * O * O * O; pos += BDIM) {
        int oz = pos % O; int t = pos / O;
        int oy = t % O;   t /= O;
        int ox = t % O;   int ow = t / O;

        float acc[COUT];
        #pragma unroll
        for (int c = 0; c < COUT; c++) acc[c] = bias[c];

        #pragma unroll 1
        for (int cin = 0; cin < CIN; cin++)
        #pragma unroll 1
        for (int kw = 0; kw < K; kw++)
        #pragma unroll 1
        for (int kx = 0; kx < K; kx++) {
            const float* plane = si + ((cin * S + ow + kw) * S + ox + kx) * S * S;
            #pragma unroll
            for (int ky = 0; ky < K; ky++) {
                const float* r  = plane + (oy + ky) * S + oz;
                const float* wp = sw + ((((cin*K + kw)*K + kx)*K + ky) * K) * COUT;
                #pragma unroll
                for (int kz = 0; kz < K; kz++)
                #pragma unroll
                for (int c = 0; c < COUT; c++)
                    acc[c] = fmaf(r[kz], wp[kz * COUT + c], acc[c]);
            }
        }
        float* outb = out + (size_t)b * COUT * O * O * O * O;
        #pragma unroll
        for (int c = 0; c < COUT; c++)
            outb[(((c * O + ow) * O + ox) * O + oy) * O + oz] = fmaxf(acc[c], 0.f);
    }
}

// ---------------------------------------------------------------------------
// Fused dense1(relu) + dense2 + softmax. One block per batch row.
// ---------------------------------------------------------------------------
__global__ __launch_bounds__(256)
void dense_head(const float* __restrict__ h, const float* __restrict__ dw1,
                const float* __restrict__ db1, const float* __restrict__ dw2,
                const float* __restrict__ db2, float* __restrict__ out)
{
    __shared__ float srow[1280];
    __shared__ float g[33];
    const int b = blockIdx.x, tid = threadIdx.x;

    for (int i = tid; i < 1280; i += 256) srow[i] = h[b * 1280 + i];
    __syncthreads();

    const int f = tid >> 2, p = tid & 3;
    float s = 0.f;
    if (f < 33) {
        const float* wrow = dw1 + f * 1280;
        for (int k = p; k < 1280; k += 4) s = fmaf(srow[k], wrow[k], s);
    }
    s += __shfl_xor_sync(0xffffffffu, s, 1);
    s += __shfl_xor_sync(0xffffffffu, s, 2);
    if (p == 0 && f < 33) g[f] = fmaxf(s + db1[f], 0.f);
    __syncthreads();

    if (tid == 0) {
        float l0 = db2[0], l1 = db2[1];
        #pragma unroll
        for (int j = 0; j < 33; j++) {
            l0 = fmaf(g[j], dw2[j], l0);
            l1 = fmaf(g[j], dw2[33 + j], l1);
        }
        float m  = fmaxf(l0, l1);
        float e0 = expf(l0 - m), e1 = expf(l1 - m);
        float inv = 1.f / (e0 + e1);
        out[b * 2 + 0] = e0 * inv;
        out[b * 2 + 1] = e1 * inv;
    }
}

// ---------------------------------------------------------------------------
extern "C" void kernel_launch(void* const* d_in, const int* in_sizes, int n_in,
                              void* d_out, int out_size)
{
    (void)in_sizes; (void)n_in; (void)out_size;
    const float* x   = (const float*)d_in[0];
    const float* w1  = (const float*)d_in[1];  const float* b1  = (const float*)d_in[2];
    const float* w2  = (const float*)d_in[3];  const float* b2  = (const float*)d_in[4];
    const float* w3  = (const float*)d_in[5];  const float* b3  = (const float*)d_in[6];
    const float* w4  = (const float*)d_in[7];  const float* b4  = (const float*)d_in[8];
    const float* w5  = (const float*)d_in[9];  const float* b5  = (const float*)d_in[10];
    const float* dw1 = (const float*)d_in[11]; const float* db1 = (const float*)d_in[12];
    const float* dw2 = (const float*)d_in[13]; const float* db2 = (const float*)d_in[14];
    float* out = (float*)d_out;

    void *p1, *p2, *p3, *p4, *p5;
    cudaGetSymbolAddress(&p1, g_h1);
    cudaGetSymbolAddress(&p2, g_h2);
    cudaGetSymbolAddress(&p3, g_h3);
    cudaGetSymbolAddress(&p4, g_h4);
    cudaGetSymbolAddress(&p5, g_h5);
    float *h1 = (float*)p1, *h2 = (float*)p2, *h3 = (float*)p3,
          *h4 = (float*)p4, *h5 = (float*)p5;

    // smem bytes: weights (u64 dup pairs) + input chunk (float)
    constexpr int SM1 = 3*1*256*8 + 1*18*18*7*7*4;   //  6144 + 63504  = 69.6 KB
    constexpr int SM2 = 3*3*256*8 + 1*15*15*5*7*4;   // 18432 + 31500  = 49.9 KB
    constexpr int SM3 = 4*3*256*8 + 1*12*12*6*5*4;   // 24576 + 17280  = 41.9 KB
    constexpr int SM4 = 5*4*256*8 + 2*9*9*9*9*4;     // 40960 + 52488  = 93.4 KB
    constexpr int SM5 = (5*6*6*6*6 + 5*5*81) * 4;    //  34.0 KB

    // L1: CIN=1,COUT=3,S=18,K=4, CCH=1, TY=4,TZ=4, BDIM=256 (O=15 -> 16 y/z tiles)
    cudaFuncSetAttribute((const void*)conv4d_yz_f2<1,3,18,4,1,4,4,256,2>,
                         cudaFuncAttributeMaxDynamicSharedMemorySize, SM1);
    // L2: CIN=3,COUT=3,S=15,K=4, CCH=1, TY=2,TZ=4, BDIM=160 (O=12 -> 18 tiles)
    cudaFuncSetAttribute((const void*)conv4d_yz_f2<3,3,15,4,1,2,4,160,4>,
                         cudaFuncAttributeMaxDynamicSharedMemorySize, SM2);
    // L3: CIN=3,COUT=4,S=12,K=4, CCH=1, TY=3,TZ=2, BDIM=96 (O=9 -> 15 tiles)
    cudaFuncSetAttribute((const void*)conv4d_yz_f2<3,4,12,4,1,3,2,96,5>,
                         cudaFuncAttributeMaxDynamicSharedMemorySize, SM3);
    // L4: CIN=4,COUT=5,S=9,K=4, CCH=2, BDIM=224
    cudaFuncSetAttribute((const void*)conv4d_fullz_f2<4,5,9,4,2,224,2>,
                         cudaFuncAttributeMaxDynamicSharedMemorySize, SM4);
    cudaFuncSetAttribute((const void*)conv4d_point<5,5,6,3,256>,
                         cudaFuncAttributeMaxDynamicSharedMemorySize, SM5);

    conv4d_yz_f2<1,3,18,4,1,4,4,256,2><<<BATCH*4*4, 256, SM1>>>(x,  w1, b1, h1);
    conv4d_yz_f2<3,3,15,4,1,2,4,160,4><<<BATCH*6*3, 160, SM2>>>(h1, w2, b2, h2);
    conv4d_yz_f2<3,4,12,4,1,3,2,96,5><<<BATCH*3*5,  96, SM3>>>(h2, w3, b3, h3);
    conv4d_fullz_f2<4,5,9,4,2,224,2><<<BATCH, 224, SM4>>>(h3, w4, b4, h4);
    conv4d_point<5,5,6,3,256><<<BATCH, 256, SM5>>>(h4, w5, b5, h5);
    dense_head<<<BATCH, 256>>>(h5, dw1, db1, dw2, db2, out);
}

// round 3
// speedup vs baseline: 1.3279x; 1.1219x over previous
#include <cuda_runtime.h>

#define BATCH 256

// ---------------- intermediate scratch (device globals; no allocs) ----------
__device__ float g_h1[BATCH*3*15*15*15*15];   // 155.5 MB
__device__ float g_h2[BATCH*3*12*12*12*12];   //  63.7 MB
__device__ float g_h3[BATCH*4*9*9*9*9];       //  26.9 MB
__device__ float g_h4[BATCH*5*6*6*6*6];       //   6.6 MB
__device__ float g_h5[BATCH*5*4*4*4*4];       //   1.3 MB

typedef unsigned long long u64;

__device__ __forceinline__ u64 pk2(float lo, float hi) {
    u64 d; asm("mov.b64 %0, {%1, %2};" : "=l"(d) : "f"(lo), "f"(hi)); return d;
}
__device__ __forceinline__ void unpk2(u64 v, float& lo, float& hi) {
    asm("mov.b64 {%0, %1}, %2;" : "=f"(lo), "=f"(hi) : "l"(v));
}
__device__ __forceinline__ u64 fma2(u64 a, u64 b, u64 c) {
    u64 d; asm("fma.rn.f32x2 %0, %1, %2, %3;" : "=l"(d) : "l"(a), "l"(b), "l"(c));
    return d;
}

// ---------------------------------------------------------------------------
// Batch-paired 4D conv (FFMA2 over two batch images; zero repacking).
// Block = (batch-pair, y-tile, z-tile). Input staged in SMEM as interleaved
// (b0,b1) u64 pairs; weights as duplicated u64 pairs. Inner loop is pure
// LDS.64 + fma.rn.f32x2. cin staged in CCH chunks, acc persists in regs.
// ---------------------------------------------------------------------------
template<int CIN,int COUT,int S,int K,int CCH,int TY,int TZ,int BDIM,int MINB>
__global__ __launch_bounds__(BDIM, MINB)
void conv4d_yz_bp(const float* __restrict__ in, const float* __restrict__ wt,
                  const float* __restrict__ bias, float* __restrict__ out)
{
    constexpr int O   = S - K + 1;
    static_assert(BDIM >= O * O, "one pos pass required");
    constexpr int TYI = TY + K - 1, TZI = TZ + K - 1;
    constexpr int NTY = (O + TY - 1) / TY, NTZ = (O + TZ - 1) / TZ;
    constexpr int ISZ = CCH * S * S * TYI * TZI;        // u64 entries per chunk
    constexpr int WSZ = COUT * CIN * K * K * K * K;     // u64 entries
    constexpr int NCH = (CIN + CCH - 1) / CCH;

    extern __shared__ u64 smu[];
    u64* sw2 = smu;            // duplicated weight pairs
    u64* siu = smu + WSZ;      // batch-interleaved input pairs

    const int tid = threadIdx.x;
    int bid = blockIdx.x;
    const int tzb = bid % NTZ; bid /= NTZ;
    const int tyb = bid % NTY;
    const int bp  = bid / NTY;                 // batch pair index
    const int y0 = tyb * TY, z0 = tzb * TZ;

    // weights: gmem [c][cin][kw][kx][ky][kz] -> smem pairs [cin][kw][kx][ky][kz][c]
    for (int i = tid; i < WSZ; i += BDIM) {
        int c = i / (CIN*K*K*K*K);
        int r = i - c * (CIN*K*K*K*K);
        float w = wt[i];
        sw2[r * COUT + c] = pk2(w, w);
    }

    const int pos = tid;
    const int ow  = pos / O, ox = pos - ow * O;
    const bool active = (pos < O * O);

    u64 acc[COUT][TY][TZ];
    #pragma unroll
    for (int c = 0; c < COUT; c++) {
        float bv = bias[c];
        u64 bpk = pk2(bv, bv);
        #pragma unroll
        for (int ty = 0; ty < TY; ty++)
            #pragma unroll
            for (int tz = 0; tz < TZ; tz++) acc[c][ty][tz] = bpk;
    }

    const float* inb0 = in + (size_t)(2*bp)     * CIN * S * S * S * S;
    const float* inb1 = in + (size_t)(2*bp + 1) * CIN * S * S * S * S;

    for (int cc = 0; cc < NCH; cc++) {
        __syncthreads();
        for (int i = tid; i < ISZ; i += BDIM) {
            int zz = i % TZI; int t = i / TZI;
            int iy = t % TYI; t /= TYI;
            int xx = t % S;   t /= S;
            int ww = t % S;   int ci = t / S;
            int gy = y0 + iy, gz = z0 + zz;
            float v0 = 0.f, v1 = 0.f;
            if (gy < S && gz < S) {
                size_t gidx = ((((size_t)(cc*CCH + ci) * S + ww) * S + xx) * S + gy) * S + gz;
                v0 = inb0[gidx];
                v1 = inb1[gidx];
            }
            siu[i] = pk2(v0, v1);
        }
        __syncthreads();

        if (active) {
            #pragma unroll
            for (int ci = 0; ci < CCH; ci++)
            #pragma unroll 1
            for (int kw = 0; kw < K; kw++)
            #pragma unroll 1
            for (int kx = 0; kx < K; kx++) {
                const u64* ip = siu + ((ci * S + ow + kw) * S + ox + kx) * TYI * TZI;
                const u64* wb = sw2 + ((((cc*CCH + ci) * K + kw) * K + kx) * K) * K * COUT;
                #pragma unroll
                for (int ky = 0; ky < K; ky++) {
                    u64 wr[K * COUT];                 // LDS.64 broadcast hoist
                    #pragma unroll
                    for (int i = 0; i < K * COUT; i++) wr[i] = wb[ky * K * COUT + i];
                    #pragma unroll
                    for (int ty = 0; ty < TY; ty++) {
                        const u64* rp0 = ip + (ky + ty) * TZI;
                        u64 row[TZI];
                        #pragma unroll
                        for (int z = 0; z < TZI; z++) row[z] = rp0[z];
                        #pragma unroll
                        for (int kz = 0; kz < K; kz++)
                        #pragma unroll
                        for (int tz = 0; tz < TZ; tz++)
                        #pragma unroll
                        for (int c = 0; c < COUT; c++)
                            acc[c][ty][tz] = fma2(row[tz + kz], wr[kz*COUT + c],
                                                  acc[c][ty][tz]);
                    }
                }
            }
        }
    }

    if (active) {
        float* outb0 = out + (size_t)(2*bp)     * COUT * O * O * O * O;
        float* outb1 = out + (size_t)(2*bp + 1) * COUT * O * O * O * O;
        #pragma unroll
        for (int c = 0; c < COUT; c++)
        #pragma unroll
        for (int ty = 0; ty < TY; ty++)
        #pragma unroll
        for (int tz = 0; tz < TZ; tz++) {
            float lo, hi; unpk2(acc[c][ty][tz], lo, hi);
            int oy = y0 + ty, oz = z0 + tz;
            if (oy < O && oz < O) {
                size_t idx = (((size_t)(c * O + ow) * O + ox) * O + oy) * O + oz;
                outb0[idx] = fmaxf(lo, 0.f);
                outb1[idx] = fmaxf(hi, 0.f);
            }
        }
    }
}

// ---------------------------------------------------------------------------
// Batch-paired whole-spatial conv (L4), with W-split for grid size.
// Thread = (owl,ox,oy); full Z held as u64 accumulators. cin chunked.
// ---------------------------------------------------------------------------
template<int CIN,int COUT,int S,int K,int CCH,int WSPLIT,int BDIM,int MINB>
__global__ __launch_bounds__(BDIM, MINB)
void conv4d_fullz_bp(const float* __restrict__ in, const float* __restrict__ wt,
                     const float* __restrict__ bias, float* __restrict__ out)
{
    constexpr int O    = S - K + 1;
    constexpr int OWT  = O / WSPLIT;           // ow per block
    constexpr int WT   = OWT + K - 1;          // staged w-slabs
    static_assert(O % WSPLIT == 0 && BDIM >= OWT * O * O, "");
    constexpr int ISZ = CCH * WT * S * S * S;  // u64 entries per chunk
    constexpr int WSZ = COUT * CIN * K * K * K * K;
    constexpr int NCH = (CIN + CCH - 1) / CCH;

    extern __shared__ u64 smu[];
    u64* sw2 = smu;
    u64* siu = smu + WSZ;

    const int tid = threadIdx.x;
    const int ws  = blockIdx.x % WSPLIT;
    const int bp  = blockIdx.x / WSPLIT;
    const int w0  = ws * OWT;

    for (int i = tid; i < WSZ; i += BDIM) {
        int c = i / (CIN*K*K*K*K);
        int r = i - c * (CIN*K*K*K*K);
        float w = wt[i];
        sw2[r * COUT + c] = pk2(w, w);
    }

    const int pos = tid;
    int oy = pos % O, t0 = pos / O;
    int ox = t0 % O, owl = t0 / O;
    const bool active = (pos < OWT * O * O);

    u64 acc[COUT][O];
    #pragma unroll
    for (int c = 0; c < COUT; c++) {
        float bv = bias[c];
        u64 bpk = pk2(bv, bv);
        #pragma unroll
        for (int z = 0; z < O; z++) acc[c][z] = bpk;
    }

    const float* inb0 = in + (size_t)(2*bp)     * CIN * S * S * S * S;
    const float* inb1 = in + (size_t)(2*bp + 1) * CIN * S * S * S * S;

    for (int cc = 0; cc < NCH; cc++) {
        __syncthreads();
        for (int i = tid; i < ISZ; i += BDIM) {
            int zz = i % S; int t = i / S;
            int yy = t % S; t /= S;
            int xx = t % S; t /= S;
            int wl = t % WT; int ci = t / WT;
            size_t gidx = ((((size_t)(cc*CCH + ci) * S + (w0 + wl)) * S + xx) * S + yy) * S + zz;
            siu[i] = pk2(inb0[gidx], inb1[gidx]);
        }
        __syncthreads();

        if (active) {
            #pragma unroll
            for (int ci = 0; ci < CCH; ci++)
            #pragma unroll 1
            for (int kw = 0; kw < K; kw++)
            #pragma unroll 1
            for (int kx = 0; kx < K; kx++) {
                const u64* plane = siu + ((ci * WT + owl + kw) * S + ox + kx) * S * S;
                const u64* wb = sw2 + ((((cc*CCH + ci) * K + kw) * K + kx) * K) * K * COUT;
                #pragma unroll
                for (int ky = 0; ky < K; ky++) {
                    u64 wr[K * COUT];
                    #pragma unroll
                    for (int i = 0; i < K * COUT; i++) wr[i] = wb[ky * K * COUT + i];
                    const u64* rowp = plane + (oy + ky) * S;
                    u64 row[S];
                    #pragma unroll
                    for (int z = 0; z < S; z++) row[z] = rowp[z];
                    #pragma unroll
                    for (int kz = 0; kz < K; kz++)
                    #pragma unroll
                    for (int z = 0; z < O; z++)
                    #pragma unroll
                    for (int c = 0; c < COUT; c++)
                        acc[c][z] = fma2(row[z + kz], wr[kz*COUT + c], acc[c][z]);
                }
            }
        }
    }

    if (active) {
        const int ow = w0 + owl;
        float* outb0 = out + (size_t)(2*bp)     * COUT * O * O * O * O;
        float* outb1 = out + (size_t)(2*bp + 1) * COUT * O * O * O * O;
        #pragma unroll
        for (int c = 0; c < COUT; c++)
        #pragma unroll
        for (int z = 0; z < O; z++) {
            float lo, hi; unpk2(acc[c][z], lo, hi);
            size_t idx = (((size_t)(c * O + ow) * O + ox) * O + oy) * O + z;
            outb0[idx] = fmaxf(lo, 0.f);
            outb1[idx] = fmaxf(hi, 0.f);
        }
    }
}

// ---------------------------------------------------------------------------
// Tiny last conv: thread = one (ow,ox,oy,oz) point, all COUT channels (scalar).
// ---------------------------------------------------------------------------
template<int CIN,int COUT,int S,int K,int BDIM>
__global__ __launch_bounds__(BDIM)
void conv4d_point(const float* __restrict__ in, const float* __restrict__ wt,
                  const float* __restrict__ bias, float* __restrict__ out)
{
    constexpr int O   = S - K + 1;
    constexpr int ISZ = CIN * S * S * S * S;
    constexpr int WSZ = COUT * CIN * K * K * K * K;
    extern __shared__ float sm[];
    float* si = sm; float* sw = sm + ISZ;
    const int tid = threadIdx.x, b = blockIdx.x;

    for (int i = tid; i < WSZ; i += BDIM) {
        int c = i / (CIN*K*K*K*K); int r = i - c * (CIN*K*K*K*K);
        sw[r * COUT + c] = wt[i];
    }
    const float* inb = in + (size_t)b * ISZ;
    for (int i = tid; i < ISZ; i += BDIM) si[i] = inb[i];
    __syncthreads();

    for (int pos = tid; pos < O * O * O * O; pos += BDIM) {
        int oz = pos % O; int t = pos / O;
        int oy = t % O;   t /= O;
        int ox = t % O;   int ow = t / O;

        float acc[COUT];
        #pragma unroll
        for (int c = 0; c < COUT; c++) acc[c] = bias[c];

        #pragma unroll 1
        for (int cin = 0; cin < CIN; cin++)
        #pragma unroll 1
        for (int kw = 0; kw < K; kw++)
        #pragma unroll 1
        for (int kx = 0; kx < K; kx++) {
            const float* plane = si + ((cin * S + ow + kw) * S + ox + kx) * S * S;
            #pragma unroll
            for (int ky = 0; ky < K; ky++) {
                const float* r  = plane + (oy + ky) * S + oz;
                const float* wp = sw + ((((cin*K + kw)*K + kx)*K + ky) * K) * COUT;
                #pragma unroll
                for (int kz = 0; kz < K; kz++)
                #pragma unroll
                for (int c = 0; c < COUT; c++)
                    acc[c] = fmaf(r[kz], wp[kz * COUT + c], acc[c]);
            }
        }
        float* outb = out + (size_t)b * COUT * O * O * O * O;
        #pragma unroll
        for (int c = 0; c < COUT; c++)
            outb[(((c * O + ow) * O + ox) * O + oy) * O + oz] = fmaxf(acc[c], 0.f);
    }
}

// ---------------------------------------------------------------------------
// Fused dense1(relu) + dense2 + softmax. One block per batch row.
// ---------------------------------------------------------------------------
__global__ __launch_bounds__(256)
void dense_head(const float* __restrict__ h, const float* __restrict__ dw1,
                const float* __restrict__ db1, const float* __restrict__ dw2,
                const float* __restrict__ db2, float* __restrict__ out)
{
    __shared__ float srow[1280];
    __shared__ float g[33];
    const int b = blockIdx.x, tid = threadIdx.x;

    for (int i = tid; i < 1280; i += 256) srow[i] = h[b * 1280 + i];
    __syncthreads();

    const int f = tid >> 2, p = tid & 3;
    float s = 0.f;
    if (f < 33) {
        const float* wrow = dw1 + f * 1280;
        for (int k = p; k < 1280; k += 4) s = fmaf(srow[k], wrow[k], s);
    }
    s += __shfl_xor_sync(0xffffffffu, s, 1);
    s += __shfl_xor_sync(0xffffffffu, s, 2);
    if (p == 0 && f < 33) g[f] = fmaxf(s + db1[f], 0.f);
    __syncthreads();

    if (tid == 0) {
        float l0 = db2[0], l1 = db2[1];
        #pragma unroll
        for (int j = 0; j < 33; j++) {
            l0 = fmaf(g[j], dw2[j], l0);
            l1 = fmaf(g[j], dw2[33 + j], l1);
        }
        float m  = fmaxf(l0, l1);
        float e0 = expf(l0 - m), e1 = expf(l1 - m);
        float inv = 1.f / (e0 + e1);
        out[b * 2 + 0] = e0 * inv;
        out[b * 2 + 1] = e1 * inv;
    }
}

// ---------------------------------------------------------------------------
extern "C" void kernel_launch(void* const* d_in, const int* in_sizes, int n_in,
                              void* d_out, int out_size)
{
    (void)in_sizes; (void)n_in; (void)out_size;
    const float* x   = (const float*)d_in[0];
    const float* w1  = (const float*)d_in[1];  const float* b1  = (const float*)d_in[2];
    const float* w2  = (const float*)d_in[3];  const float* b2  = (const float*)d_in[4];
    const float* w3  = (const float*)d_in[5];  const float* b3  = (const float*)d_in[6];
    const float* w4  = (const float*)d_in[7];  const float* b4  = (const float*)d_in[8];
    const float* w5  = (const float*)d_in[9];  const float* b5  = (const float*)d_in[10];
    const float* dw1 = (const float*)d_in[11]; const float* db1 = (const float*)d_in[12];
    const float* dw2 = (const float*)d_in[13]; const float* db2 = (const float*)d_in[14];
    float* out = (float*)d_out;

    void *p1, *p2, *p3, *p4, *p5;
    cudaGetSymbolAddress(&p1, g_h1);
    cudaGetSymbolAddress(&p2, g_h2);
    cudaGetSymbolAddress(&p3, g_h3);
    cudaGetSymbolAddress(&p4, g_h4);
    cudaGetSymbolAddress(&p5, g_h5);
    float *h1 = (float*)p1, *h2 = (float*)p2, *h3 = (float*)p3,
          *h4 = (float*)p4, *h5 = (float*)p5;

    // smem bytes: weights (u64 dup pairs) + batch-interleaved input (u64)
    constexpr int SM1 = (3*1*256 + 1*18*18*5*7) * 8;   //  6144 + 90720 = 94.6 KB
    constexpr int SM2 = (3*3*256 + 1*15*15*5*7) * 8;   // 18432 + 63000 = 79.5 KB
    constexpr int SM3 = (4*3*256 + 1*12*12*5*6) * 8;   // 24576 + 34560 = 57.8 KB
    constexpr int SM4 = (5*4*256 + 2*6*9*9*9)   * 8;   // 40960 + 69984 = 108.3 KB
    constexpr int SM5 = (5*6*6*6*6 + 5*5*81) * 4;      //  34.0 KB

    // L1: CIN=1,COUT=3,S=18,K=4, CCH=1, TY=2,TZ=4, BDIM=256 (O=15: NTY=8,NTZ=4)
    cudaFuncSetAttribute((const void*)conv4d_yz_bp<1,3,18,4,1,2,4,256,2>,
                         cudaFuncAttributeMaxDynamicSharedMemorySize, SM1);
    // L2: CIN=3,COUT=3,S=15,K=4, CCH=1, TY=2,TZ=4, BDIM=160 (O=12: NTY=6,NTZ=3)
    cudaFuncSetAttribute((const void*)conv4d_yz_bp<3,3,15,4,1,2,4,160,2>,
                         cudaFuncAttributeMaxDynamicSharedMemorySize, SM2);
    // L3: CIN=3,COUT=4,S=12,K=4, CCH=1, TY=2,TZ=3, BDIM=96 (O=9: NTY=5,NTZ=3)
    cudaFuncSetAttribute((const void*)conv4d_yz_bp<3,4,12,4,1,2,3,96,3>,
                         cudaFuncAttributeMaxDynamicSharedMemorySize, SM3);
    // L4: CIN=4,COUT=5,S=9,K=4, CCH=2, WSPLIT=2, BDIM=128
    cudaFuncSetAttribute((const void*)conv4d_fullz_bp<4,5,9,4,2,2,128,2>,
                         cudaFuncAttributeMaxDynamicSharedMemorySize, SM4);
    cudaFuncSetAttribute((const void*)conv4d_point<5,5,6,3,256>,
                         cudaFuncAttributeMaxDynamicSharedMemorySize, SM5);

    constexpr int NBP = BATCH / 2;   // 128 batch pairs

    conv4d_yz_bp<1,3,18,4,1,2,4,256,2><<<NBP*8*4, 256, SM1>>>(x,  w1, b1, h1);
    conv4d_yz_bp<3,3,15,4,1,2,4,160,2><<<NBP*6*3, 160, SM2>>>(h1, w2, b2, h2);
    conv4d_yz_bp<3,4,12,4,1,2,3,96,3><<<NBP*5*3,  96, SM3>>>(h2, w3, b3, h3);
    conv4d_fullz_bp<4,5,9,4,2,2,128,2><<<NBP*2, 128, SM4>>>(h3, w4, b4, h4);
    conv4d_point<5,5,6,3,256><<<BATCH, 256, SM5>>>(h4, w5, b5, h5);
    dense_head<<<BATCH, 256>>>(h5, dw1, db1, dw2, db2, out);
}

// round 4
// speedup vs baseline: 1.5563x; 1.1720x over previous
#include <cuda_runtime.h>

#define BATCH 256

// ---------------- intermediate scratch (device globals; no allocs) ----------
__device__ float g_h1[BATCH*3*15*15*15*15];   // 155.5 MB
__device__ float g_h2[BATCH*3*12*12*12*12];   //  63.7 MB
__device__ float g_h3[BATCH*4*9*9*9*9];       //  26.9 MB
__device__ float g_h4[BATCH*5*6*6*6*6];       //   6.6 MB
__device__ float g_h5[BATCH*5*4*4*4*4];       //   1.3 MB

typedef unsigned long long u64;

__device__ __forceinline__ u64 pk2(float lo, float hi) {
    u64 d; asm("mov.b64 %0, {%1, %2};" : "=l"(d) : "f"(lo), "f"(hi)); return d;
}
__device__ __forceinline__ void unpk2(u64 v, float& lo, float& hi) {
    asm("mov.b64 {%0, %1}, %2;" : "=f"(lo), "=f"(hi) : "l"(v));
}
__device__ __forceinline__ u64 fma2(u64 a, u64 b, u64 c) {
    u64 d; asm("fma.rn.f32x2 %0, %1, %2, %3;" : "=l"(d) : "l"(a), "l"(b), "l"(c));
    return d;
}

// ---------------------------------------------------------------------------
// Batch-paired 4D conv (FFMA2 over two batch images; zero repacking).
// Block = (batch-pair, y-tile, z-tile). Per-CHUNK weight staging keeps SMEM
// small -> 2-4 CTAs/SM. Inner loop: LDS.64 + fma.rn.f32x2 only.
// ---------------------------------------------------------------------------
template<int CIN,int COUT,int S,int K,int CCH,int TY,int TZ,int BDIM,int MINB>
__global__ __launch_bounds__(BDIM, MINB)
void conv4d_yz_bp(const float* __restrict__ in, const float* __restrict__ wt,
                  const float* __restrict__ bias, float* __restrict__ out)
{
    constexpr int O   = S - K + 1;
    static_assert(BDIM >= O * O, "one pos pass required");
    constexpr int K4  = K * K * K * K;
    constexpr int TYI = TY + K - 1, TZI = TZ + K - 1;
    constexpr int NTY = (O + TY - 1) / TY, NTZ = (O + TZ - 1) / TZ;
    constexpr int ISZ = CCH * S * S * TYI * TZI;        // u64 entries per chunk
    constexpr int WCH = COUT * CCH * K4;                // u64 entries per chunk
    constexpr int NCH = (CIN + CCH - 1) / CCH;

    extern __shared__ u64 smu[];
    u64* sw2 = smu;            // duplicated weight pairs (current chunk)
    u64* siu = smu + WCH;      // batch-interleaved input pairs (current chunk)

    const int tid = threadIdx.x;
    int bid = blockIdx.x;
    const int tzb = bid % NTZ; bid /= NTZ;
    const int tyb = bid % NTY;
    const int bp  = bid / NTY;                 // batch pair index
    const int y0 = tyb * TY, z0 = tzb * TZ;

    const int pos = tid;
    const int ow  = pos / O, ox = pos - ow * O;
    const bool active = (pos < O * O);

    u64 acc[COUT][TY][TZ];
    #pragma unroll
    for (int c = 0; c < COUT; c++) {
        float bv = bias[c];
        u64 bpk = pk2(bv, bv);
        #pragma unroll
        for (int ty = 0; ty < TY; ty++)
            #pragma unroll
            for (int tz = 0; tz < TZ; tz++) acc[c][ty][tz] = bpk;
    }

    const float* inb0 = in + (size_t)(2*bp)     * CIN * S * S * S * S;
    const float* inb1 = in + (size_t)(2*bp + 1) * CIN * S * S * S * S;

    for (int cc = 0; cc < NCH; cc++) {
        __syncthreads();
        // stage this chunk's weights: gmem [c][cin][k4] -> smem [ci][k4][c] pairs
        for (int i = tid; i < WCH; i += BDIM) {
            int c = i / (CCH * K4);
            int r = i - c * (CCH * K4);
            float w = wt[(c * CIN + cc * CCH) * K4 + r];
            sw2[r * COUT + c] = pk2(w, w);
        }
        // stage this chunk's input tile
        for (int i = tid; i < ISZ; i += BDIM) {
            int zz = i % TZI; int t = i / TZI;
            int iy = t % TYI; t /= TYI;
            int xx = t % S;   t /= S;
            int ww = t % S;   int ci = t / S;
            int gy = y0 + iy, gz = z0 + zz;
            float v0 = 0.f, v1 = 0.f;
            if (gy < S && gz < S) {
                size_t gidx = ((((size_t)(cc*CCH + ci) * S + ww) * S + xx) * S + gy) * S + gz;
                v0 = inb0[gidx];
                v1 = inb1[gidx];
            }
            siu[i] = pk2(v0, v1);
        }
        __syncthreads();

        if (active) {
            #pragma unroll
            for (int ci = 0; ci < CCH; ci++)
            #pragma unroll 1
            for (int kw = 0; kw < K; kw++)
            #pragma unroll 1
            for (int kx = 0; kx < K; kx++) {
                const u64* ip = siu + ((ci * S + ow + kw) * S + ox + kx) * TYI * TZI;
                const u64* wb = sw2 + (((ci * K + kw) * K + kx) * K) * K * COUT;
                #pragma unroll
                for (int ky = 0; ky < K; ky++) {
                    u64 wr[K * COUT];                 // LDS.64 broadcast hoist
                    #pragma unroll
                    for (int i = 0; i < K * COUT; i++) wr[i] = wb[ky * K * COUT + i];
                    #pragma unroll
                    for (int ty = 0; ty < TY; ty++) {
                        const u64* rp0 = ip + (ky + ty) * TZI;
                        u64 row[TZI];
                        #pragma unroll
                        for (int z = 0; z < TZI; z++) row[z] = rp0[z];
                        #pragma unroll
                        for (int kz = 0; kz < K; kz++)
                        #pragma unroll
                        for (int tz = 0; tz < TZ; tz++)
                        #pragma unroll
                        for (int c = 0; c < COUT; c++)
                            acc[c][ty][tz] = fma2(row[tz + kz], wr[kz*COUT + c],
                                                  acc[c][ty][tz]);
                    }
                }
            }
        }
    }

    if (active) {
        float* outb0 = out + (size_t)(2*bp)     * COUT * O * O * O * O;
        float* outb1 = out + (size_t)(2*bp + 1) * COUT * O * O * O * O;
        #pragma unroll
        for (int c = 0; c < COUT; c++)
        #pragma unroll
        for (int ty = 0; ty < TY; ty++)
        #pragma unroll
        for (int tz = 0; tz < TZ; tz++) {
            float lo, hi; unpk2(acc[c][ty][tz], lo, hi);
            int oy = y0 + ty, oz = z0 + tz;
            if (oy < O && oz < O) {
                size_t idx = (((size_t)(c * O + ow) * O + ox) * O + oy) * O + oz;
                outb0[idx] = fmaxf(lo, 0.f);
                outb1[idx] = fmaxf(hi, 0.f);
            }
        }
    }
}

// ---------------------------------------------------------------------------
// Batch-paired whole-spatial conv (L4), W-split, per-chunk weights.
// Thread = (owl,ox,oy); full Z held as u64 accumulators. cin chunked.
// ---------------------------------------------------------------------------
template<int CIN,int COUT,int S,int K,int CCH,int WSPLIT,int BDIM,int MINB>
__global__ __launch_bounds__(BDIM, MINB)
void conv4d_fullz_bp(const float* __restrict__ in, const float* __restrict__ wt,
                     const float* __restrict__ bias, float* __restrict__ out)
{
    constexpr int O    = S - K + 1;
    constexpr int K4   = K * K * K * K;
    constexpr int OWT  = O / WSPLIT;           // ow per block
    constexpr int WT   = OWT + K - 1;          // staged w-slabs
    static_assert(O % WSPLIT == 0 && BDIM >= OWT * O * O, "");
    constexpr int ISZ = CCH * WT * S * S * S;  // u64 entries per chunk
    constexpr int WCH = COUT * CCH * K4;
    constexpr int NCH = (CIN + CCH - 1) / CCH;

    extern __shared__ u64 smu[];
    u64* sw2 = smu;
    u64* siu = smu + WCH;

    const int tid = threadIdx.x;
    const int ws  = blockIdx.x % WSPLIT;
    const int bp  = blockIdx.x / WSPLIT;
    const int w0  = ws * OWT;

    const int pos = tid;
    int oy = pos % O, t0 = pos / O;
    int ox = t0 % O, owl = t0 / O;
    const bool active = (pos < OWT * O * O);

    u64 acc[COUT][O];
    #pragma unroll
    for (int c = 0; c < COUT; c++) {
        float bv = bias[c];
        u64 bpk = pk2(bv, bv);
        #pragma unroll
        for (int z = 0; z < O; z++) acc[c][z] = bpk;
    }

    const float* inb0 = in + (size_t)(2*bp)     * CIN * S * S * S * S;
    const float* inb1 = in + (size_t)(2*bp + 1) * CIN * S * S * S * S;

    for (int cc = 0; cc < NCH; cc++) {
        __syncthreads();
        for (int i = tid; i < WCH; i += BDIM) {
            int c = i / (CCH * K4);
            int r = i - c * (CCH * K4);
            float w = wt[(c * CIN + cc * CCH) * K4 + r];
            sw2[r * COUT + c] = pk2(w, w);
        }
        for (int i = tid; i < ISZ; i += BDIM) {
            int zz = i % S; int t = i / S;
            int yy = t % S; t /= S;
            int xx = t % S; t /= S;
            int wl = t % WT; int ci = t / WT;
            size_t gidx = ((((size_t)(cc*CCH + ci) * S + (w0 + wl)) * S + xx) * S + yy) * S + zz;
            siu[i] = pk2(inb0[gidx], inb1[gidx]);
        }
        __syncthreads();

        if (active) {
            #pragma unroll
            for (int ci = 0; ci < CCH; ci++)
            #pragma unroll 1
            for (int kw = 0; kw < K; kw++)
            #pragma unroll 1
            for (int kx = 0; kx < K; kx++) {
                const u64* plane = siu + ((ci * WT + owl + kw) * S + ox + kx) * S * S;
                const u64* wb = sw2 + (((ci * K + kw) * K + kx) * K) * K * COUT;
                #pragma unroll
                for (int ky = 0; ky < K; ky++) {
                    u64 wr[K * COUT];
                    #pragma unroll
                    for (int i = 0; i < K * COUT; i++) wr[i] = wb[ky * K * COUT + i];
                    const u64* rowp = plane + (oy + ky) * S;
                    u64 row[S];
                    #pragma unroll
                    for (int z = 0; z < S; z++) row[z] = rowp[z];
                    #pragma unroll
                    for (int kz = 0; kz < K; kz++)
                    #pragma unroll
                    for (int z = 0; z < O; z++)
                    #pragma unroll
                    for (int c = 0; c < COUT; c++)
                        acc[c][z] = fma2(row[z + kz], wr[kz*COUT + c], acc[c][z]);
                }
            }
        }
    }

    if (active) {
        const int ow = w0 + owl;
        float* outb0 = out + (size_t)(2*bp)     * COUT * O * O * O * O;
        float* outb1 = out + (size_t)(2*bp + 1) * COUT * O * O * O * O;
        #pragma unroll
        for (int c = 0; c < COUT; c++)
        #pragma unroll
        for (int z = 0; z < O; z++) {
            float lo, hi; unpk2(acc[c][z], lo, hi);
            size_t idx = (((size_t)(c * O + ow) * O + ox) * O + oy) * O + z;
            outb0[idx] = fmaxf(lo, 0.f);
            outb1[idx] = fmaxf(hi, 0.f);
        }
    }
}

// ---------------------------------------------------------------------------
// Tiny last conv: thread = one (ow,ox,oy,oz) point, all COUT channels (scalar).
// ---------------------------------------------------------------------------
template<int CIN,int COUT,int S,int K,int BDIM>
__global__ __launch_bounds__(BDIM)
void conv4d_point(const float* __restrict__ in, const float* __restrict__ wt,
                  const float* __restrict__ bias, float* __restrict__ out)
{
    constexpr int O   = S - K + 1;
    constexpr int ISZ = CIN * S * S * S * S;
    constexpr int WSZ = COUT * CIN * K * K * K * K;
    extern __shared__ float sm[];
    float* si = sm; float* sw = sm + ISZ;
    const int tid = threadIdx.x, b = blockIdx.x;

    for (int i = tid; i < WSZ; i += BDIM) {
        int c = i / (CIN*K*K*K*K); int r = i - c * (CIN*K*K*K*K);
        sw[r * COUT + c] = wt[i];
    }
    const float* inb = in + (size_t)b * ISZ;
    for (int i = tid; i < ISZ; i += BDIM) si[i] = inb[i];
    __syncthreads();

    for (int pos = tid; pos < O * O * O * O; pos += BDIM) {
        int oz = pos % O; int t = pos / O;
        int oy = t % O;   t /= O;
        int ox = t % O;   int ow = t / O;

        float acc[COUT];
        #pragma unroll
        for (int c = 0; c < COUT; c++) acc[c] = bias[c];

        #pragma unroll 1
        for (int cin = 0; cin < CIN; cin++)
        #pragma unroll 1
        for (int kw = 0; kw < K; kw++)
        #pragma unroll 1
        for (int kx = 0; kx < K; kx++) {
            const float* plane = si + ((cin * S + ow + kw) * S + ox + kx) * S * S;
            #pragma unroll
            for (int ky = 0; ky < K; ky++) {
                const float* r  = plane + (oy + ky) * S + oz;
                const float* wp = sw + ((((cin*K + kw)*K + kx)*K + ky) * K) * COUT;
                #pragma unroll
                for (int kz = 0; kz < K; kz++)
                #pragma unroll
                for (int c = 0; c < COUT; c++)
                    acc[c] = fmaf(r[kz], wp[kz * COUT + c], acc[c]);
            }
        }
        float* outb = out + (size_t)b * COUT * O * O * O * O;
        #pragma unroll
        for (int c = 0; c < COUT; c++)
            outb[(((c * O + ow) * O + ox) * O + oy) * O + oz] = fmaxf(acc[c], 0.f);
    }
}

// ---------------------------------------------------------------------------
// Fused dense1(relu) + dense2 + softmax. One block per batch row.
// ---------------------------------------------------------------------------
__global__ __launch_bounds__(256)
void dense_head(const float* __restrict__ h, const float* __restrict__ dw1,
                const float* __restrict__ db1, const float* __restrict__ dw2,
                const float* __restrict__ db2, float* __restrict__ out)
{
    __shared__ float srow[1280];
    __shared__ float g[33];
    const int b = blockIdx.x, tid = threadIdx.x;

    for (int i = tid; i < 1280; i += 256) srow[i] = h[b * 1280 + i];
    __syncthreads();

    const int f = tid >> 2, p = tid & 3;
    float s = 0.f;
    if (f < 33) {
        const float* wrow = dw1 + f * 1280;
        for (int k = p; k < 1280; k += 4) s = fmaf(srow[k], wrow[k], s);
    }
    s += __shfl_xor_sync(0xffffffffu, s, 1);
    s += __shfl_xor_sync(0xffffffffu, s, 2);
    if (p == 0 && f < 33) g[f] = fmaxf(s + db1[f], 0.f);
    __syncthreads();

    if (tid == 0) {
        float l0 = db2[0], l1 = db2[1];
        #pragma unroll
        for (int j = 0; j < 33; j++) {
            l0 = fmaf(g[j], dw2[j], l0);
            l1 = fmaf(g[j], dw2[33 + j], l1);
        }
        float m  = fmaxf(l0, l1);
        float e0 = expf(l0 - m), e1 = expf(l1 - m);
        float inv = 1.f / (e0 + e1);
        out[b * 2 + 0] = e0 * inv;
        out[b * 2 + 1] = e1 * inv;
    }
}

// ---------------------------------------------------------------------------
extern "C" void kernel_launch(void* const* d_in, const int* in_sizes, int n_in,
                              void* d_out, int out_size)
{
    (void)in_sizes; (void)n_in; (void)out_size;
    const float* x   = (const float*)d_in[0];
    const float* w1  = (const float*)d_in[1];  const float* b1  = (const float*)d_in[2];
    const float* w2  = (const float*)d_in[3];  const float* b2  = (const float*)d_in[4];
    const float* w3  = (const float*)d_in[5];  const float* b3  = (const float*)d_in[6];
    const float* w4  = (const float*)d_in[7];  const float* b4  = (const float*)d_in[8];
    const float* w5  = (const float*)d_in[9];  const float* b5  = (const float*)d_in[10];
    const float* dw1 = (const float*)d_in[11]; const float* db1 = (const float*)d_in[12];
    const float* dw2 = (const float*)d_in[13]; const float* db2 = (const float*)d_in[14];
    float* out = (float*)d_out;

    void *p1, *p2, *p3, *p4, *p5;
    cudaGetSymbolAddress(&p1, g_h1);
    cudaGetSymbolAddress(&p2, g_h2);
    cudaGetSymbolAddress(&p3, g_h3);
    cudaGetSymbolAddress(&p4, g_h4);
    cudaGetSymbolAddress(&p5, g_h5);
    float *h1 = (float*)p1, *h2 = (float*)p2, *h3 = (float*)p3,
          *h4 = (float*)p4, *h5 = (float*)p5;

    // smem bytes: per-chunk weights (u64 pairs) + batch-interleaved input (u64)
    constexpr int SM1 = (3*1*256 + 18*18*5*7) * 8;   // 96,864  -> 2 CTAs/SM
    constexpr int SM2 = (3*1*256 + 15*15*5*7) * 8;   // 69,144  -> 3 CTAs/SM
    constexpr int SM3 = (4*1*256 + 12*12*6*6) * 8;   // 49,664  -> 4 CTAs/SM
    constexpr int SM4 = (5*1*256 + 6*9*9*9)   * 8;   // 45,232  -> 3 CTAs/SM (regs)
    constexpr int SM5 = (5*6*6*6*6 + 5*5*81) * 4;    // 34.0 KB

    // L1: CIN=1,COUT=3,S=18,K=4, CCH=1, TY=2,TZ=4 (NTY=8,NTZ=4), BDIM=256
    cudaFuncSetAttribute((const void*)conv4d_yz_bp<1,3,18,4,1,2,4,256,2>,
                         cudaFuncAttributeMaxDynamicSharedMemorySize, SM1);
    // L2: CIN=3,COUT=3,S=15,K=4, CCH=1, TY=2,TZ=4 (NTY=6,NTZ=3), BDIM=160
    cudaFuncSetAttribute((const void*)conv4d_yz_bp<3,3,15,4,1,2,4,160,3>,
                         cudaFuncAttributeMaxDynamicSharedMemorySize, SM2);
    // L3: CIN=3,COUT=4,S=12,K=4, CCH=1, TY=3,TZ=3 (NTY=3,NTZ=3 exact), BDIM=96
    cudaFuncSetAttribute((const void*)conv4d_yz_bp<3,4,12,4,1,3,3,96,4>,
                         cudaFuncAttributeMaxDynamicSharedMemorySize, SM3);
    // L4: CIN=4,COUT=5,S=9,K=4, CCH=1, WSPLIT=2, BDIM=128
    cudaFuncSetAttribute((const void*)conv4d_fullz_bp<4,5,9,4,1,2,128,3>,
                         cudaFuncAttributeMaxDynamicSharedMemorySize, SM4);
    cudaFuncSetAttribute((const void*)conv4d_point<5,5,6,3,256>,
                         cudaFuncAttributeMaxDynamicSharedMemorySize, SM5);

    constexpr int NBP = BATCH / 2;   // 128 batch pairs

    conv4d_yz_bp<1,3,18,4,1,2,4,256,2><<<NBP*8*4, 256, SM1>>>(x,  w1, b1, h1);
    conv4d_yz_bp<3,3,15,4,1,2,4,160,3><<<NBP*6*3, 160, SM2>>>(h1, w2, b2, h2);
    conv4d_yz_bp<3,4,12,4,1,3,3,96,4><<<NBP*3*3,  96, SM3>>>(h2, w3, b3, h3);
    conv4d_fullz_bp<4,5,9,4,1,2,128,3><<<NBP*2, 128, SM4>>>(h3, w4, b4, h4);
    conv4d_point<5,5,6,3,256><<<BATCH, 256, SM5>>>(h4, w5, b5, h5);
    dense_head<<<BATCH, 256>>>(h5, dw1, db1, dw2, db2, out);
}